// round 1
// baseline (speedup 1.0000x reference)
#include <cuda_runtime.h>
#include <math_constants.h>

#define BB 8
#define NN 4096
#define KNN 20
#define EPSV 1e-5f
#define SLOPE 0.2f
#define NTOT ((float)(BB*NN*KNN))
#define PTS 16

__device__ int   g_idx[BB*NN*KNN];
__device__ float g_mom[27];
__device__ float g_scale1[64], g_shift1[64];
__device__ float g_sum2[64], g_sumsq2[64];
__device__ float g_scale2[64], g_shift2[64];
__device__ float g_maxb[BB*NN*64];
__device__ float g_minb[BB*NN*64];

__global__ void zero_kernel() {
    int t = threadIdx.x;
    if (t < 27) g_mom[t] = 0.f;
    if (t < 64) { g_sum2[t] = 0.f; g_sumsq2[t] = 0.f; }
}

// KNN (top-20 by squared distance, self included) + fused edge moment reduction.
// One thread per query point; all points of the batch in smem.
__global__ __launch_bounds__(128) void knn_kernel(const float* __restrict__ x) {
    __shared__ float sx[NN], sy[NN], sz[NN];
    int b = blockIdx.y;
    int tid = threadIdx.x;
    const float* xb = x + b * 3 * NN;
    for (int i = tid; i < NN; i += 128) {
        sx[i] = xb[i];
        sy[i] = xb[NN + i];
        sz[i] = xb[2 * NN + i];
    }
    __syncthreads();

    int q = blockIdx.x * 128 + tid;
    float qx = sx[q], qy = sy[q], qz = sz[q];
    float dl[KNN]; int il[KNN];
#pragma unroll
    for (int j = 0; j < KNN; j++) { dl[j] = CUDART_INF_F; il[j] = 0; }

    for (int m = 0; m < NN; m++) {
        float dx = qx - sx[m], dy = qy - sy[m], dz = qz - sz[m];
        float d = dx * dx; d = fmaf(dy, dy, d); d = fmaf(dz, dz, d);
        if (d < dl[KNN - 1]) {
            float cd = d; int ci = m;
#pragma unroll
            for (int j = 0; j < KNN; j++) {
                if (cd < dl[j]) {
                    float td = dl[j]; int ti = il[j];
                    dl[j] = cd; il[j] = ci;
                    cd = td; ci = ti;
                }
            }
        }
    }

    int base = (b * NN + q) * KNN;
#pragma unroll
    for (int j = 0; j < KNN; j++) g_idx[base + j] = il[j];

    // Edge moments: first moment (6) + upper-tri second moment (21).
    float acc[27];
#pragma unroll
    for (int i = 0; i < 27; i++) acc[i] = 0.f;
#pragma unroll
    for (int j = 0; j < KNN; j++) {
        int m = il[j];
        float e[6];
        e[0] = sx[m] - qx; e[1] = sy[m] - qy; e[2] = sz[m] - qz;
        e[3] = qx; e[4] = qy; e[5] = qz;
        int t = 6;
#pragma unroll
        for (int a = 0; a < 6; a++) {
            acc[a] += e[a];
#pragma unroll
            for (int bb = a; bb < 6; bb++) acc[t++] += e[a] * e[bb];
        }
    }
#pragma unroll
    for (int i = 0; i < 27; i++) {
#pragma unroll
        for (int o = 16; o > 0; o >>= 1)
            acc[i] += __shfl_xor_sync(0xffffffffu, acc[i], o);
    }
    if ((tid & 31) == 0) {
#pragma unroll
        for (int i = 0; i < 27; i++) atomicAdd(&g_mom[i], acc[i]);
    }
}

// BN1 stats from edge moments: mean = W1c . s / NT ; E[h^2] = W1c^T M W1c / NT
__global__ void stats1_kernel(const float* __restrict__ W1,
                              const float* __restrict__ gamma1,
                              const float* __restrict__ beta1) {
    int c = threadIdx.x;
    if (c >= 64) return;
    float w[6];
#pragma unroll
    for (int j = 0; j < 6; j++) w[j] = W1[c * 6 + j];
    float m = 0.f;
#pragma unroll
    for (int j = 0; j < 6; j++) m += w[j] * g_mom[j];
    m /= NTOT;
    float qv = 0.f;
    int t = 6;
#pragma unroll
    for (int a = 0; a < 6; a++) {
#pragma unroll
        for (int bb = a; bb < 6; bb++) {
            float coef = (a == bb) ? 1.f : 2.f;
            qv += coef * w[a] * w[bb] * g_mom[t++];
        }
    }
    qv /= NTOT;
    float var = qv - m * m;
    float s = gamma1[c] * rsqrtf(var + EPSV);
    g_scale1[c] = s;
    g_shift1[c] = fmaf(-m, s, beta1[c]);
}

// Main fused kernel: edges -> h1 -> BN1+LReLU -> h2 (64x64) -> {max_k, min_k, sum, sumsq}
// 128 threads, 16 points per block, 2 points processed concurrently (one per 64-thread half).
__global__ __launch_bounds__(128) void main_kernel(const float* __restrict__ x,
                                                   const float* __restrict__ W1,
                                                   const float* __restrict__ W2) {
    __shared__ __align__(16) float sedge[2][KNN][8];
    __shared__ __align__(16) float sg[2][KNN][64];
    __shared__ float sredA[128], sredB[128];

    int tid = threadIdx.x;
    int half = tid >> 6;
    int c = tid & 63;
    int pt0 = blockIdx.x * PTS;
    int b = pt0 >> 12;
    int n0 = pt0 & (NN - 1);

    float w2row[64];
#pragma unroll
    for (int j = 0; j < 64; j++) w2row[j] = W2[c * 64 + j];
    float w1row[6];
#pragma unroll
    for (int j = 0; j < 6; j++) w1row[j] = W1[c * 6 + j];
    float s1 = g_scale1[c], sh1 = g_shift1[c];
    float sum2 = 0.f, ssq2 = 0.f;
    const float* xb = x + b * 3 * NN;

    for (int p = 0; p < PTS; p += 2) {
        int pt = n0 + p + half;
        int gi = b * NN + pt;
        __syncthreads();
        if (c < KNN) {
            int k = c;
            int nb = g_idx[gi * KNN + k];
            float qx = xb[pt], qy = xb[NN + pt], qz = xb[2 * NN + pt];
            float px = xb[nb], py = xb[NN + nb], pz = xb[2 * NN + nb];
            sedge[half][k][0] = px - qx;
            sedge[half][k][1] = py - qy;
            sedge[half][k][2] = pz - qz;
            sedge[half][k][3] = qx;
            sedge[half][k][4] = qy;
            sedge[half][k][5] = qz;
        }
        __syncthreads();
#pragma unroll
        for (int k = 0; k < KNN; k++) {
            float h = 0.f;
#pragma unroll
            for (int j = 0; j < 6; j++) h = fmaf(sedge[half][k][j], w1row[j], h);
            float v = fmaf(s1, h, sh1);
            sg[half][k][c] = fmaxf(v, SLOPE * v);
        }
        __syncthreads();
        float mx = -CUDART_INF_F, mn = CUDART_INF_F;
#pragma unroll 2
        for (int k = 0; k < KNN; k++) {
            float h0 = 0.f, h1 = 0.f, h2a = 0.f, h3 = 0.f;
#pragma unroll
            for (int j = 0; j < 64; j += 4) {
                float4 gv = *(const float4*)&sg[half][k][j];
                h0  = fmaf(gv.x, w2row[j + 0], h0);
                h1  = fmaf(gv.y, w2row[j + 1], h1);
                h2a = fmaf(gv.z, w2row[j + 2], h2a);
                h3  = fmaf(gv.w, w2row[j + 3], h3);
            }
            float h = (h0 + h1) + (h2a + h3);
            mx = fmaxf(mx, h);
            mn = fminf(mn, h);
            sum2 += h;
            ssq2 = fmaf(h, h, ssq2);
        }
        g_maxb[gi * 64 + c] = mx;
        g_minb[gi * 64 + c] = mn;
    }

    sredA[tid] = sum2;
    sredB[tid] = ssq2;
    __syncthreads();
    if (tid < 64) {
        atomicAdd(&g_sum2[tid],   sredA[tid] + sredA[tid + 64]);
        atomicAdd(&g_sumsq2[tid], sredB[tid] + sredB[tid + 64]);
    }
}

__global__ void stats2_kernel(const float* __restrict__ gamma2,
                              const float* __restrict__ beta2) {
    int c = threadIdx.x;
    if (c >= 64) return;
    float mean = g_sum2[c] / NTOT;
    float var = g_sumsq2[c] / NTOT - mean * mean;
    float s = gamma2[c] * rsqrtf(var + EPSV);
    g_scale2[c] = s;
    g_shift2[c] = fmaf(-mean, s, beta2[c]);
}

// Epilogue: out[b][c][n] = lrelu(s2*(s2>=0 ? max_k : min_k) + t2), transposed via smem tile.
__global__ __launch_bounds__(256) void out_kernel(float* __restrict__ out) {
    __shared__ float tile[64][65];
    int b = blockIdx.y;
    int n0 = blockIdx.x * 64;
    int tid = threadIdx.x;
#pragma unroll
    for (int i = 0; i < 16; i++) {
        int flat = i * 256 + tid;
        int cc = flat & 63;
        int nl = flat >> 6;
        float s = g_scale2[cc];
        int gi = (b * NN + n0 + nl) * 64 + cc;
        float v;
        if (s >= 0.f) v = g_maxb[gi]; else v = g_minb[gi];
        float u = fmaf(s, v, g_shift2[cc]);
        tile[nl][cc] = fmaxf(u, SLOPE * u);
    }
    __syncthreads();
#pragma unroll
    for (int i = 0; i < 16; i++) {
        int flat = i * 256 + tid;
        int nl = flat & 63;
        int cc = flat >> 6;
        out[(b * 64 + cc) * NN + n0 + nl] = tile[nl][cc];
    }
}

extern "C" void kernel_launch(void* const* d_in, const int* in_sizes, int n_in,
                              void* d_out, int out_size) {
    const float* x      = (const float*)d_in[0];
    const float* W1     = (const float*)d_in[1];
    const float* gamma1 = (const float*)d_in[2];
    const float* beta1  = (const float*)d_in[3];
    const float* W2     = (const float*)d_in[4];
    const float* gamma2 = (const float*)d_in[5];
    const float* beta2  = (const float*)d_in[6];
    float* out = (float*)d_out;

    zero_kernel<<<1, 64>>>();
    knn_kernel<<<dim3(NN / 128, BB), 128>>>(x);
    stats1_kernel<<<1, 64>>>(W1, gamma1, beta1);
    main_kernel<<<BB * NN / PTS, 128>>>(x, W1, W2);
    stats2_kernel<<<1, 64>>>(gamma2, beta2);
    out_kernel<<<dim3(NN / 64, BB), 256>>>(out);
}

// round 2
// speedup vs baseline: 2.0306x; 2.0306x over previous
#include <cuda_runtime.h>
#include <math_constants.h>

#define BB 8
#define NN 4096
#define KNN 20
#define EPSV 1e-5f
#define SLOPE 0.2f
#define NTOT ((float)(BB*NN*KNN))
#define PTS 16

__device__ int   g_idx[BB*NN*KNN];
__device__ float g_mom[27];
__device__ float g_scale1[64], g_shift1[64];
__device__ float g_sum2[64], g_sumsq2[64];
__device__ float g_scale2[64], g_shift2[64];
__device__ float g_maxb[BB*NN*64];
__device__ float g_minb[BB*NN*64];

__global__ void zero_kernel() {
    int t = threadIdx.x;
    if (t < 27) g_mom[t] = 0.f;
    if (t < 64) { g_sum2[t] = 0.f; g_sumsq2[t] = 0.f; }
}

// KNN with lazy-batched selection: candidates passing the (stale) 20th-distance
// threshold are appended to a small per-thread buffer (predicated, no branch);
// buffers are merged into the sorted top-20 registers in warp-collective
// compactions. Processing order stays ascending-m with strict '<', so the
// selected set is identical to a serial insertion scan.
__global__ __launch_bounds__(64) void knn_kernel(const float* __restrict__ x) {
    __shared__ float sx[NN], sy[NN], sz[NN];
    int b = blockIdx.y;
    int tid = threadIdx.x;
    const float* xb = x + b * 3 * NN;
    for (int i = tid; i < NN; i += 64) {
        sx[i] = xb[i];
        sy[i] = xb[NN + i];
        sz[i] = xb[2 * NN + i];
    }
    __syncthreads();

    int q = blockIdx.x * 64 + tid;
    float qx = sx[q], qy = sy[q], qz = sz[q];
    float dl[KNN]; int il[KNN];
#pragma unroll
    for (int j = 0; j < KNN; j++) { dl[j] = CUDART_INF_F; il[j] = 0; }

    unsigned short buf[32];
    int cnt = 0;

    for (int m0 = 0; m0 < NN; m0 += 8) {
        float d[8];
#pragma unroll
        for (int u = 0; u < 8; u++) {
            int m = m0 + u;
            float dx = qx - sx[m], dy = qy - sy[m], dz = qz - sz[m];
            d[u] = fmaf(dx, dx, fmaf(dy, dy, dz * dz));
        }
        float thr = dl[KNN - 1];
#pragma unroll
        for (int u = 0; u < 8; u++) {
            if (d[u] < thr) buf[cnt++] = (unsigned short)(m0 + u);
        }
        if (__any_sync(0xffffffffu, cnt >= 24)) {
            for (int i = 0; i < cnt; i++) {
                int m = buf[i];
                float dx = qx - sx[m], dy = qy - sy[m], dz = qz - sz[m];
                float dd = fmaf(dx, dx, fmaf(dy, dy, dz * dz));
                if (dd < dl[KNN - 1]) {
                    float cd = dd; int ci = m;
#pragma unroll
                    for (int j = 0; j < KNN; j++) {
                        if (cd < dl[j]) {
                            float td = dl[j]; int ti = il[j];
                            dl[j] = cd; il[j] = ci;
                            cd = td; ci = ti;
                        }
                    }
                }
            }
            cnt = 0;
        }
    }
    // flush remaining buffered candidates
    for (int i = 0; i < cnt; i++) {
        int m = buf[i];
        float dx = qx - sx[m], dy = qy - sy[m], dz = qz - sz[m];
        float dd = fmaf(dx, dx, fmaf(dy, dy, dz * dz));
        if (dd < dl[KNN - 1]) {
            float cd = dd; int ci = m;
#pragma unroll
            for (int j = 0; j < KNN; j++) {
                if (cd < dl[j]) {
                    float td = dl[j]; int ti = il[j];
                    dl[j] = cd; il[j] = ci;
                    cd = td; ci = ti;
                }
            }
        }
    }

    int base = (b * NN + q) * KNN;
#pragma unroll
    for (int j = 0; j < KNN; j++) g_idx[base + j] = il[j];

    // Edge moments: first moment (6) + upper-tri second moment (21).
    float acc[27];
#pragma unroll
    for (int i = 0; i < 27; i++) acc[i] = 0.f;
#pragma unroll
    for (int j = 0; j < KNN; j++) {
        int m = il[j];
        float e[6];
        e[0] = sx[m] - qx; e[1] = sy[m] - qy; e[2] = sz[m] - qz;
        e[3] = qx; e[4] = qy; e[5] = qz;
        int t = 6;
#pragma unroll
        for (int a = 0; a < 6; a++) {
            acc[a] += e[a];
#pragma unroll
            for (int bb = a; bb < 6; bb++) acc[t++] += e[a] * e[bb];
        }
    }
#pragma unroll
    for (int i = 0; i < 27; i++) {
#pragma unroll
        for (int o = 16; o > 0; o >>= 1)
            acc[i] += __shfl_xor_sync(0xffffffffu, acc[i], o);
    }
    if ((tid & 31) == 0) {
#pragma unroll
        for (int i = 0; i < 27; i++) atomicAdd(&g_mom[i], acc[i]);
    }
}

// BN1 stats from edge moments: mean = W1c . s / NT ; E[h^2] = W1c^T M W1c / NT
__global__ void stats1_kernel(const float* __restrict__ W1,
                              const float* __restrict__ gamma1,
                              const float* __restrict__ beta1) {
    int c = threadIdx.x;
    if (c >= 64) return;
    float w[6];
#pragma unroll
    for (int j = 0; j < 6; j++) w[j] = W1[c * 6 + j];
    float m = 0.f;
#pragma unroll
    for (int j = 0; j < 6; j++) m += w[j] * g_mom[j];
    m /= NTOT;
    float qv = 0.f;
    int t = 6;
#pragma unroll
    for (int a = 0; a < 6; a++) {
#pragma unroll
        for (int bb = a; bb < 6; bb++) {
            float coef = (a == bb) ? 1.f : 2.f;
            qv += coef * w[a] * w[bb] * g_mom[t++];
        }
    }
    qv /= NTOT;
    float var = qv - m * m;
    float s = gamma1[c] * rsqrtf(var + EPSV);
    g_scale1[c] = s;
    g_shift1[c] = fmaf(-m, s, beta1[c]);
}

// Main fused kernel: edges -> h1 -> BN1+LReLU -> h2 (64x64) -> {max_k, min_k, sum, sumsq}
__global__ __launch_bounds__(128) void main_kernel(const float* __restrict__ x,
                                                   const float* __restrict__ W1,
                                                   const float* __restrict__ W2) {
    __shared__ __align__(16) float sedge[2][KNN][8];
    __shared__ __align__(16) float sg[2][KNN][64];
    __shared__ float sredA[128], sredB[128];

    int tid = threadIdx.x;
    int half = tid >> 6;
    int c = tid & 63;
    int pt0 = blockIdx.x * PTS;
    int b = pt0 >> 12;
    int n0 = pt0 & (NN - 1);

    float w2row[64];
#pragma unroll
    for (int j = 0; j < 64; j++) w2row[j] = W2[c * 64 + j];
    float w1row[6];
#pragma unroll
    for (int j = 0; j < 6; j++) w1row[j] = W1[c * 6 + j];
    float s1 = g_scale1[c], sh1 = g_shift1[c];
    float sum2 = 0.f, ssq2 = 0.f;
    const float* xb = x + b * 3 * NN;

    for (int p = 0; p < PTS; p += 2) {
        int pt = n0 + p + half;
        int gi = b * NN + pt;
        __syncthreads();
        if (c < KNN) {
            int k = c;
            int nb = g_idx[gi * KNN + k];
            float qx = xb[pt], qy = xb[NN + pt], qz = xb[2 * NN + pt];
            float px = xb[nb], py = xb[NN + nb], pz = xb[2 * NN + nb];
            sedge[half][k][0] = px - qx;
            sedge[half][k][1] = py - qy;
            sedge[half][k][2] = pz - qz;
            sedge[half][k][3] = qx;
            sedge[half][k][4] = qy;
            sedge[half][k][5] = qz;
        }
        __syncthreads();
#pragma unroll
        for (int k = 0; k < KNN; k++) {
            float h = 0.f;
#pragma unroll
            for (int j = 0; j < 6; j++) h = fmaf(sedge[half][k][j], w1row[j], h);
            float v = fmaf(s1, h, sh1);
            sg[half][k][c] = fmaxf(v, SLOPE * v);
        }
        __syncthreads();
        float mx = -CUDART_INF_F, mn = CUDART_INF_F;
#pragma unroll 2
        for (int k = 0; k < KNN; k++) {
            float h0 = 0.f, h1 = 0.f, h2a = 0.f, h3 = 0.f;
#pragma unroll
            for (int j = 0; j < 64; j += 4) {
                float4 gv = *(const float4*)&sg[half][k][j];
                h0  = fmaf(gv.x, w2row[j + 0], h0);
                h1  = fmaf(gv.y, w2row[j + 1], h1);
                h2a = fmaf(gv.z, w2row[j + 2], h2a);
                h3  = fmaf(gv.w, w2row[j + 3], h3);
            }
            float h = (h0 + h1) + (h2a + h3);
            mx = fmaxf(mx, h);
            mn = fminf(mn, h);
            sum2 += h;
            ssq2 = fmaf(h, h, ssq2);
        }
        g_maxb[gi * 64 + c] = mx;
        g_minb[gi * 64 + c] = mn;
    }

    sredA[tid] = sum2;
    sredB[tid] = ssq2;
    __syncthreads();
    if (tid < 64) {
        atomicAdd(&g_sum2[tid],   sredA[tid] + sredA[tid + 64]);
        atomicAdd(&g_sumsq2[tid], sredB[tid] + sredB[tid + 64]);
    }
}

__global__ void stats2_kernel(const float* __restrict__ gamma2,
                              const float* __restrict__ beta2) {
    int c = threadIdx.x;
    if (c >= 64) return;
    float mean = g_sum2[c] / NTOT;
    float var = g_sumsq2[c] / NTOT - mean * mean;
    float s = gamma2[c] * rsqrtf(var + EPSV);
    g_scale2[c] = s;
    g_shift2[c] = fmaf(-mean, s, beta2[c]);
}

// Epilogue: out[b][c][n] = lrelu(s2*(s2>=0 ? max_k : min_k) + t2), transposed via smem tile.
__global__ __launch_bounds__(256) void out_kernel(float* __restrict__ out) {
    __shared__ float tile[64][65];
    int b = blockIdx.y;
    int n0 = blockIdx.x * 64;
    int tid = threadIdx.x;
#pragma unroll
    for (int i = 0; i < 16; i++) {
        int flat = i * 256 + tid;
        int cc = flat & 63;
        int nl = flat >> 6;
        float s = g_scale2[cc];
        int gi = (b * NN + n0 + nl) * 64 + cc;
        float v;
        if (s >= 0.f) v = g_maxb[gi]; else v = g_minb[gi];
        float u = fmaf(s, v, g_shift2[cc]);
        tile[nl][cc] = fmaxf(u, SLOPE * u);
    }
    __syncthreads();
#pragma unroll
    for (int i = 0; i < 16; i++) {
        int flat = i * 256 + tid;
        int nl = flat & 63;
        int cc = flat >> 6;
        out[(b * 64 + cc) * NN + n0 + nl] = tile[nl][cc];
    }
}

extern "C" void kernel_launch(void* const* d_in, const int* in_sizes, int n_in,
                              void* d_out, int out_size) {
    const float* x      = (const float*)d_in[0];
    const float* W1     = (const float*)d_in[1];
    const float* gamma1 = (const float*)d_in[2];
    const float* beta1  = (const float*)d_in[3];
    const float* W2     = (const float*)d_in[4];
    const float* gamma2 = (const float*)d_in[5];
    const float* beta2  = (const float*)d_in[6];
    float* out = (float*)d_out;

    zero_kernel<<<1, 64>>>();
    knn_kernel<<<dim3(NN / 64, BB), 64>>>(x);
    stats1_kernel<<<1, 64>>>(W1, gamma1, beta1);
    main_kernel<<<BB * NN / PTS, 128>>>(x, W1, W2);
    stats2_kernel<<<1, 64>>>(gamma2, beta2);
    out_kernel<<<dim3(NN / 64, BB), 256>>>(out);
}

// round 3
// speedup vs baseline: 2.2851x; 1.1253x over previous
#include <cuda_runtime.h>
#include <math_constants.h>

#define BB 8
#define NN 4096
#define KNN 20
#define EPSV 1e-5f
#define SLOPE 0.2f
#define NTOT ((float)(BB*NN*KNN))
#define PTS 16

typedef unsigned long long ull;

__device__ __forceinline__ void fma2(ull& d, ull a, ull b) {
    asm("fma.rn.f32x2 %0, %1, %2, %0;" : "+l"(d) : "l"(a), "l"(b));
}
__device__ __forceinline__ ull add2(ull a, ull b) {
    ull r; asm("add.rn.f32x2 %0, %1, %2;" : "=l"(r) : "l"(a), "l"(b)); return r;
}
__device__ __forceinline__ ull pack2(float lo, float hi) {
    ull r; asm("mov.b64 %0, {%1, %2};" : "=l"(r) : "f"(lo), "f"(hi)); return r;
}
__device__ __forceinline__ void unpack2(ull v, float& lo, float& hi) {
    asm("mov.b64 {%0, %1}, %2;" : "=f"(lo), "=f"(hi) : "l"(v));
}

__device__ int   g_idx[BB*NN*KNN];
__device__ float g_mom[27];
__device__ float g_scale1[64], g_shift1[64];
__device__ float g_sum2[64], g_sumsq2[64];
__device__ float g_scale2[64], g_shift2[64];
__device__ float g_maxb[BB*NN*64];
__device__ float g_minb[BB*NN*64];

__global__ void zero_kernel() {
    int t = threadIdx.x;
    if (t < 27) g_mom[t] = 0.f;
    if (t < 64) { g_sum2[t] = 0.f; g_sumsq2[t] = 0.f; }
}

// Branchless PARALLEL insertion of (dd, m) into sorted top-20 (caller
// guarantees dd < dl[KNN-1]). Each slot reads only OLD values (descending
// in-place) -> dependency depth ~2 instead of a 20-deep swap chain.
__device__ __forceinline__ void insert20(float (&dl)[KNN], int (&il)[KNN],
                                         float dd, int m) {
#pragma unroll
    for (int j = KNN - 1; j >= 1; j--) {
        bool b1 = dd < dl[j - 1];
        bool b2 = dd < dl[j];
        dl[j] = b1 ? dl[j - 1] : (b2 ? dd : dl[j]);
        il[j] = b1 ? il[j - 1] : (b2 ? m  : il[j]);
    }
    bool b0 = dd < dl[0];
    dl[0] = b0 ? dd : dl[0];
    il[0] = b0 ? m  : il[0];
}

// KNN: thread-per-query; 8-wide distance batches; candidates passing the
// stale threshold buffered in SMEM; merged via parallel insertion in
// warp-collective compactions. Ascending-m + strict '<' => identical
// selection to a serial stable scan.
__global__ __launch_bounds__(128) void knn_kernel(const float* __restrict__ x) {
    __shared__ float sx[NN], sy[NN], sz[NN];
    __shared__ unsigned short sbuf[32][128];
    int b = blockIdx.y;
    int tid = threadIdx.x;
    const float* xb = x + b * 3 * NN;
    for (int i = tid; i < NN; i += 128) {
        sx[i] = xb[i];
        sy[i] = xb[NN + i];
        sz[i] = xb[2 * NN + i];
    }
    __syncthreads();

    int q = blockIdx.x * 128 + tid;
    float qx = sx[q], qy = sy[q], qz = sz[q];
    float dl[KNN]; int il[KNN];
#pragma unroll
    for (int j = 0; j < KNN; j++) { dl[j] = CUDART_INF_F; il[j] = 0; }

    int cnt = 0;

    for (int m0 = 0; m0 < NN; m0 += 8) {
        float d[8];
#pragma unroll
        for (int u = 0; u < 8; u++) {
            int m = m0 + u;
            float dx = qx - sx[m], dy = qy - sy[m], dz = qz - sz[m];
            d[u] = fmaf(dx, dx, fmaf(dy, dy, dz * dz));
        }
        float thr = dl[KNN - 1];
#pragma unroll
        for (int u = 0; u < 8; u++) {
            if (d[u] < thr) { sbuf[cnt][tid] = (unsigned short)(m0 + u); cnt++; }
        }
        if (__any_sync(0xffffffffu, cnt > 20)) {
            for (int i = 0; i < cnt; i++) {
                int m = sbuf[i][tid];
                float dx = qx - sx[m], dy = qy - sy[m], dz = qz - sz[m];
                float dd = fmaf(dx, dx, fmaf(dy, dy, dz * dz));
                if (dd < dl[KNN - 1]) insert20(dl, il, dd, m);
            }
            cnt = 0;
        }
    }
    for (int i = 0; i < cnt; i++) {
        int m = sbuf[i][tid];
        float dx = qx - sx[m], dy = qy - sy[m], dz = qz - sz[m];
        float dd = fmaf(dx, dx, fmaf(dy, dy, dz * dz));
        if (dd < dl[KNN - 1]) insert20(dl, il, dd, m);
    }

    int base = (b * NN + q) * KNN;
#pragma unroll
    for (int j = 0; j < KNN; j++) g_idx[base + j] = il[j];

    // Edge moments: first moment (6) + upper-tri second moment (21).
    float acc[27];
#pragma unroll
    for (int i = 0; i < 27; i++) acc[i] = 0.f;
#pragma unroll
    for (int j = 0; j < KNN; j++) {
        int m = il[j];
        float e[6];
        e[0] = sx[m] - qx; e[1] = sy[m] - qy; e[2] = sz[m] - qz;
        e[3] = qx; e[4] = qy; e[5] = qz;
        int t = 6;
#pragma unroll
        for (int a = 0; a < 6; a++) {
            acc[a] += e[a];
#pragma unroll
            for (int bb = a; bb < 6; bb++) acc[t++] += e[a] * e[bb];
        }
    }
#pragma unroll
    for (int i = 0; i < 27; i++) {
#pragma unroll
        for (int o = 16; o > 0; o >>= 1)
            acc[i] += __shfl_xor_sync(0xffffffffu, acc[i], o);
    }
    if ((tid & 31) == 0) {
#pragma unroll
        for (int i = 0; i < 27; i++) atomicAdd(&g_mom[i], acc[i]);
    }
}

__global__ void stats1_kernel(const float* __restrict__ W1,
                              const float* __restrict__ gamma1,
                              const float* __restrict__ beta1) {
    int c = threadIdx.x;
    if (c >= 64) return;
    float w[6];
#pragma unroll
    for (int j = 0; j < 6; j++) w[j] = W1[c * 6 + j];
    float m = 0.f;
#pragma unroll
    for (int j = 0; j < 6; j++) m += w[j] * g_mom[j];
    m /= NTOT;
    float qv = 0.f;
    int t = 6;
#pragma unroll
    for (int a = 0; a < 6; a++) {
#pragma unroll
        for (int bb = a; bb < 6; bb++) {
            float coef = (a == bb) ? 1.f : 2.f;
            qv += coef * w[a] * w[bb] * g_mom[t++];
        }
    }
    qv /= NTOT;
    float var = qv - m * m;
    float s = gamma1[c] * rsqrtf(var + EPSV);
    g_scale1[c] = s;
    g_shift1[c] = fmaf(-m, s, beta1[c]);
}

// Main fused kernel with f32x2-packed 64x64 GEMV.
// sg stored [pt][k][c]: phase-A writes are lane-stride-1; phase-B reads are
// broadcast ulonglong2 (two packed j-pairs per LDS.128, no repack movs).
__global__ __launch_bounds__(128) void main_kernel(const float* __restrict__ x,
                                                   const float* __restrict__ W1,
                                                   const float* __restrict__ W2) {
    __shared__ __align__(16) float sedge[2][KNN][8];
    __shared__ __align__(16) float sg[2][KNN][64];
    __shared__ float sredA[128], sredB[128];

    int tid = threadIdx.x;
    int half = tid >> 6;
    int c = tid & 63;
    int pt0 = blockIdx.x * PTS;
    int b = pt0 >> 12;
    int n0 = pt0 & (NN - 1);

    ull w2pk[32];
#pragma unroll
    for (int j = 0; j < 32; j++)
        w2pk[j] = pack2(W2[c * 64 + 2 * j], W2[c * 64 + 2 * j + 1]);
    float w1row[6];
#pragma unroll
    for (int j = 0; j < 6; j++) w1row[j] = W1[c * 6 + j];
    float s1 = g_scale1[c], sh1 = g_shift1[c];
    float sum2 = 0.f, ssq2 = 0.f;
    const float* xb = x + b * 3 * NN;

    for (int p = 0; p < PTS; p += 2) {
        int pt = n0 + p + half;
        int gi = b * NN + pt;
        __syncthreads();
        if (c < KNN) {
            int k = c;
            int nb = g_idx[gi * KNN + k];
            float qx = xb[pt], qy = xb[NN + pt], qz = xb[2 * NN + pt];
            float px = xb[nb], py = xb[NN + nb], pz = xb[2 * NN + nb];
            sedge[half][k][0] = px - qx;
            sedge[half][k][1] = py - qy;
            sedge[half][k][2] = pz - qz;
            sedge[half][k][3] = qx;
            sedge[half][k][4] = qy;
            sedge[half][k][5] = qz;
        }
        __syncthreads();
#pragma unroll
        for (int k = 0; k < KNN; k++) {
            float h = 0.f;
#pragma unroll
            for (int j = 0; j < 6; j++) h = fmaf(sedge[half][k][j], w1row[j], h);
            float v = fmaf(s1, h, sh1);
            sg[half][k][c] = fmaxf(v, SLOPE * v);
        }
        __syncthreads();
        float mx = -CUDART_INF_F, mn = CUDART_INF_F;
#pragma unroll 2
        for (int k = 0; k < KNN; k++) {
            const ulonglong2* gp = reinterpret_cast<const ulonglong2*>(&sg[half][k][0]);
            ull a0 = 0ull, a1 = 0ull, a2 = 0ull, a3 = 0ull;
#pragma unroll
            for (int i = 0; i < 16; i += 2) {
                ulonglong2 gA = gp[i];
                ulonglong2 gB = gp[i + 1];
                fma2(a0, gA.x, w2pk[2 * i + 0]);
                fma2(a1, gA.y, w2pk[2 * i + 1]);
                fma2(a2, gB.x, w2pk[2 * i + 2]);
                fma2(a3, gB.y, w2pk[2 * i + 3]);
            }
            ull s = add2(add2(a0, a1), add2(a2, a3));
            float flo, fhi;
            unpack2(s, flo, fhi);
            float h = flo + fhi;
            mx = fmaxf(mx, h);
            mn = fminf(mn, h);
            sum2 += h;
            ssq2 = fmaf(h, h, ssq2);
        }
        g_maxb[gi * 64 + c] = mx;
        g_minb[gi * 64 + c] = mn;
    }

    sredA[tid] = sum2;
    sredB[tid] = ssq2;
    __syncthreads();
    if (tid < 64) {
        atomicAdd(&g_sum2[tid],   sredA[tid] + sredA[tid + 64]);
        atomicAdd(&g_sumsq2[tid], sredB[tid] + sredB[tid + 64]);
    }
}

__global__ void stats2_kernel(const float* __restrict__ gamma2,
                              const float* __restrict__ beta2) {
    int c = threadIdx.x;
    if (c >= 64) return;
    float mean = g_sum2[c] / NTOT;
    float var = g_sumsq2[c] / NTOT - mean * mean;
    float s = gamma2[c] * rsqrtf(var + EPSV);
    g_scale2[c] = s;
    g_shift2[c] = fmaf(-mean, s, beta2[c]);
}

__global__ __launch_bounds__(256) void out_kernel(float* __restrict__ out) {
    __shared__ float tile[64][65];
    int b = blockIdx.y;
    int n0 = blockIdx.x * 64;
    int tid = threadIdx.x;
#pragma unroll
    for (int i = 0; i < 16; i++) {
        int flat = i * 256 + tid;
        int cc = flat & 63;
        int nl = flat >> 6;
        float s = g_scale2[cc];
        int gi = (b * NN + n0 + nl) * 64 + cc;
        float v;
        if (s >= 0.f) v = g_maxb[gi]; else v = g_minb[gi];
        float u = fmaf(s, v, g_shift2[cc]);
        tile[nl][cc] = fmaxf(u, SLOPE * u);
    }
    __syncthreads();
#pragma unroll
    for (int i = 0; i < 16; i++) {
        int flat = i * 256 + tid;
        int nl = flat & 63;
        int cc = flat >> 6;
        out[(b * 64 + cc) * NN + n0 + nl] = tile[nl][cc];
    }
}

extern "C" void kernel_launch(void* const* d_in, const int* in_sizes, int n_in,
                              void* d_out, int out_size) {
    const float* x      = (const float*)d_in[0];
    const float* W1     = (const float*)d_in[1];
    const float* gamma1 = (const float*)d_in[2];
    const float* beta1  = (const float*)d_in[3];
    const float* W2     = (const float*)d_in[4];
    const float* gamma2 = (const float*)d_in[5];
    const float* beta2  = (const float*)d_in[6];
    float* out = (float*)d_out;

    zero_kernel<<<1, 64>>>();
    knn_kernel<<<dim3(NN / 128, BB), 128>>>(x);
    stats1_kernel<<<1, 64>>>(W1, gamma1, beta1);
    main_kernel<<<BB * NN / PTS, 128>>>(x, W1, W2);
    stats2_kernel<<<1, 64>>>(gamma2, beta2);
    out_kernel<<<dim3(NN / 64, BB), 256>>>(out);
}